// round 3
// baseline (speedup 1.0000x reference)
#include <cuda_runtime.h>
#include <cstdint>

// ---------------- problem constants ----------------
#define BB   16
#define DD   64
#define HH   768
#define NE   7
#define ROWS (BB*DD)                 // 1024 utterances
#define PAIRS_PER_B (DD*(DD+1)/2)    // 2080
#define NPAIR (BB*PAIRS_PER_B)       // 33280

#define GRID  128
#define NTHR  256
#define NWARP (NTHR/32)              // 8
#define TOTWARP (GRID*NWARP)         // 1024
#define NGROUP (GRID*4)              // 512 two-warp groups

// ---------------- device scratch (no allocs allowed) ----------------
__device__ float g_Wc[2*1552*2];   // folded expert weights [e][j<1552][c]
__device__ float g_Ob[4];          // folded expert bias [e*2+c]
__device__ float g_T[ROWS*12];     // per-utterance table [G1(2) G2(2) O1(4) O2(4)]
__device__ float g_spk[ROWS];      // speaker ids as float
__device__ unsigned int g_bar[2];  // monotonic barrier counters (never reset)

// Software global barrier. Monotonic ticket counter -> deterministic across
// graph replays (each launch consumes exactly one "round" of GRID arrivals;
// round boundary derived from the arrival ticket itself, so no reset needed).
// Requires all GRID blocks co-resident: GRID=128 <= #SMs (148), 1 block/SM,
// tiny smem, regs << 256/thread -> guaranteed wave-1 residency.
__device__ __forceinline__ void global_barrier(int b) {
    __syncthreads();
    if (threadIdx.x == 0) {
        __threadfence();                               // publish my phase writes
        unsigned t = atomicAdd(&g_bar[b], 1u) + 1u;    // my arrival ticket
        unsigned round_end = ((t + GRID - 1u) / GRID) * GRID;
        volatile unsigned int* ctr = &g_bar[b];
        while (*ctr < round_end) { __nanosleep(64); }
        __threadfence();
    }
    __syncthreads();
}

__global__ void __launch_bounds__(NTHR)
fused_kernel(const float* __restrict__ pooled,
             const void*  __restrict__ spk_raw,
             const float* __restrict__ emo_w,
             const float* __restrict__ emo_b,
             const float* __restrict__ gate_w,
             const float* __restrict__ gate_b,
             const float* __restrict__ w1,
             const float* __restrict__ b1,
             const float* __restrict__ w2,
             const float* __restrict__ b2,
             float* __restrict__ out_emo,     // [1024*7]
             float* __restrict__ out_cause) { // [33280*2]
    const int tid  = threadIdx.x;
    const int lane = tid & 31;
    const int warp = tid >> 5;

    __shared__ float wsum[4][2][19];
    __shared__ float ep[4][7];
    __shared__ int   s_is64;

    // ================= phase A: spk convert (block 0) + fold experts =========
    if (blockIdx.x == 0) {
        // speaker_ids may be stored int64 or int32 (values in {0,1}).
        // int64: odd 32-bit words of first 1024 words are all zero.
        if (tid == 0) s_is64 = 1;
        __syncthreads();
        const unsigned int* u = (const unsigned int*)spk_raw;
        for (int i = tid; i < ROWS; i += NTHR)
            if (u[2 * i + 1] != 0u) s_is64 = 0;
        __syncthreads();
        bool w64 = (s_is64 != 0);
        for (int i = tid; i < ROWS; i += NTHR) {
            unsigned int v = w64 ? u[2 * i] : u[i];
            g_spk[i] = (float)v;
        }
    }

    // Wc[e][j][c] = sum_k w1[e][j][k] * w2[e][k][c];  one warp per row j.
    const int gwarp = blockIdx.x * NWARP + warp;
    for (int task = gwarp; task < 2 * 1552 + 4; task += TOTWARP) {
        if (task < 2 * 1552) {
            int e = task / 1552, j = task % 1552;
            const float* a  = w1 + ((size_t)e * 1552 + j) * 256;
            const float* wb = w2 + e * 512;
            float a0 = 0.f, a1 = 0.f;
            #pragma unroll 4
            for (int k = lane; k < 256; k += 32) {
                float x = a[k];
                a0 += x * wb[k * 2 + 0];
                a1 += x * wb[k * 2 + 1];
            }
            #pragma unroll
            for (int off = 16; off; off >>= 1) {
                a0 += __shfl_down_sync(0xffffffffu, a0, off);
                a1 += __shfl_down_sync(0xffffffffu, a1, off);
            }
            if (lane == 0) {
                g_Wc[task * 2 + 0] = a0;
                g_Wc[task * 2 + 1] = a1;
            }
        } else {
            int idx = task - 2 * 1552;        // 0..3
            int e = idx >> 1, c = idx & 1;
            float s = 0.f;
            for (int k = lane; k < 256; k += 32)
                s += b1[e * 256 + k] * w2[e * 512 + k * 2 + c];
            #pragma unroll
            for (int off = 16; off; off >>= 1)
                s += __shfl_down_sync(0xffffffffu, s, off);
            if (lane == 0) g_Ob[idx] = s + b2[e * 2 + c];
        }
    }

    global_barrier(0);

    // ================= phase B: per-utterance table + emotion head ===========
    // One row per 2-warp group; 4 groups/block; 512 groups -> 2 iterations.
    const int g    = warp >> 1;            // group within block 0..3
    const int half = warp & 1;             // which warp of the group
    const int gid  = blockIdx.x * 4 + g;   // global group id 0..511

    for (int rr = 0; rr < 2; rr++) {
        const int i = gid + rr * NGROUP;   // row 0..1023
        const float* row = pooled + (size_t)i * HH;

        float acc[19];
        #pragma unroll
        for (int m = 0; m < 19; m++) acc[m] = 0.f;

        for (int j = half * 32 + lane; j < HH; j += 64) {
            float x = row[j];
            #pragma unroll
            for (int c = 0; c < 7; c++) acc[c] += x * emo_w[j * 7 + c];
            acc[7]  += x * gate_w[j * 2 + 0];
            acc[8]  += x * gate_w[j * 2 + 1];
            acc[9]  += x * gate_w[(776 + j) * 2 + 0];
            acc[10] += x * gate_w[(776 + j) * 2 + 1];
            #pragma unroll
            for (int idx = 0; idx < 4; idx++) {
                int e = idx >> 1, c = idx & 1;
                acc[11 + idx] += x * g_Wc[(e * 1552 + j) * 2 + c];
                acc[15 + idx] += x * g_Wc[(e * 1552 + 776 + j) * 2 + c];
            }
        }

        #pragma unroll
        for (int off = 16; off; off >>= 1) {
            #pragma unroll
            for (int m = 0; m < 19; m++)
                acc[m] += __shfl_down_sync(0xffffffffu, acc[m], off);
        }
        if (lane == 0) {
            #pragma unroll
            for (int m = 0; m < 19; m++) wsum[g][half][m] = acc[m];
        }
        __syncthreads();

        if (half == 0 && lane < 19) {        // even warps finalize, lanes 0..18
            int m = lane;
            float s = wsum[g][0][m] + wsum[g][1][m];
            if (m < 7) {
                float v = s + emo_b[m];
                ep[g][m] = v;
                out_emo[(size_t)i * 7 + m] = v;
            }
            __syncwarp(0x0007ffffu);
            if (m >= 7) {
                float v = s;
                float spkv = g_spk[i];
                #pragma unroll
                for (int f = 768; f < 776; f++) {
                    float xf = (f == 775) ? spkv : ep[g][f - 768];
                    float w;
                    if (m < 9)        w = gate_w[f * 2 + (m - 7)];
                    else if (m < 11)  w = gate_w[(776 + f) * 2 + (m - 9)];
                    else if (m < 15) { int idx = m - 11; w = g_Wc[((idx >> 1) * 1552 + f) * 2 + (idx & 1)]; }
                    else             { int idx = m - 15; w = g_Wc[((idx >> 1) * 1552 + 776 + f) * 2 + (idx & 1)]; }
                    v += xf * w;
                }
                g_T[i * 12 + (m - 7)] = v;
            }
        }
        __syncthreads();
    }

    global_barrier(1);

    // ================= phase C: pair combine =================================
    const float gb0 = __ldg(&gate_b[0]);
    const float gb1 = __ldg(&gate_b[1]);
    for (int p = blockIdx.x * NTHR + tid; p < NPAIR; p += GRID * NTHR) {
        int b = p / PAIRS_PER_B;
        int q = p - b * PAIRS_PER_B;
        int end = (int)((sqrtf(8.f * (float)q + 1.f) - 1.f) * 0.5f);
        while ((end + 1) * (end + 2) / 2 <= q) end++;
        while (end * (end + 1) / 2 > q) end--;
        int t = q - end * (end + 1) / 2;

        const float* Tt = g_T + (b * DD + t)   * 12;
        const float* Te = g_T + (b * DD + end) * 12;

        float g0 = Tt[0] + Te[2] + gb0;
        float g1 = Tt[1] + Te[3] + gb1;

        float o00 = Tt[4] + Te[8]  + g_Ob[0];
        float o01 = Tt[5] + Te[9]  + g_Ob[1];
        float o10 = Tt[6] + Te[10] + g_Ob[2];
        float o11 = Tt[7] + Te[11] + g_Ob[3];

        out_cause[(size_t)p * 2 + 0] = g0 * o00 + g1 * o10;
        out_cause[(size_t)p * 2 + 1] = g0 * o01 + g1 * o11;
    }
}

// ---------------- launch ----------------
extern "C" void kernel_launch(void* const* d_in, const int* in_sizes, int n_in,
                              void* d_out, int out_size) {
    const float* pooled  = (const float*)d_in[0];
    const void*  spk     = d_in[1];
    const float* emo_w   = (const float*)d_in[2];
    const float* emo_b   = (const float*)d_in[3];
    const float* gate_w  = (const float*)d_in[4];
    const float* gate_b  = (const float*)d_in[5];
    const float* exp_w1  = (const float*)d_in[6];
    const float* exp_b1  = (const float*)d_in[7];
    const float* exp_w2  = (const float*)d_in[8];
    const float* exp_b2  = (const float*)d_in[9];
    float* out = (float*)d_out;

    fused_kernel<<<GRID, NTHR>>>(pooled, spk, emo_w, emo_b, gate_w, gate_b,
                                 exp_w1, exp_b1, exp_w2, exp_b2,
                                 out, out + ROWS * NE);
}

// round 4
// speedup vs baseline: 1.4783x; 1.4783x over previous
#include <cuda_runtime.h>
#include <cstdint>

// ---------------- problem constants ----------------
#define BB   16
#define DD   64
#define HH   768
#define NE   7
#define ROWS (BB*DD)                 // 1024 utterances
#define PAIRS_PER_B (DD*(DD+1)/2)    // 2080
#define NPAIR (BB*PAIRS_PER_B)       // 33280
#define FOLD_TASKS (2*1552)          // 3104

// ---------------- device scratch (no allocs allowed) ----------------
__device__ float g_Wc[2*1552*2];      // folded expert weights [e*1552+j][c]
__device__ float g_Ob[4];             // folded expert bias [e*2+c]
__device__ float g_W19[HH*20];        // packed per-j weights: [j][0:7 emo |7:9 G1 |9:11 G2 |11:15 O1 |15:19 O2 |19 pad]
__device__ float g_T[ROWS*12];        // per-utterance table [G1(2) G2(2) O1(4) O2(4)]
__device__ float g_spk[ROWS];         // speaker ids as float
__device__ unsigned int g_cnt[BB];    // per-batch monotonic sync counters (never reset)

// ================= kernel A: fold experts + pack weights + spk ==============
// grid 390 x 256 = 3120 warps:
//   warp 0..3103      : fold row (e,j):  Wc[e][j][c] = sum_k w1[e][j][k]*w2[e][k][c]
//   warp 3104..3107   : Ob[e][c] = b1[e]@w2[e][:,c] + b2[e][c]
//   warp 3108         : speaker-id dtype sniff + convert
//   warp 3109..3119   : pack emo_w / gate_w columns into g_W19
__global__ void __launch_bounds__(256)
prep_kernel(const void*  __restrict__ spk_raw,
            const float* __restrict__ emo_w,
            const float* __restrict__ gate_w,
            const float* __restrict__ w1,
            const float* __restrict__ b1,
            const float* __restrict__ w2,
            const float* __restrict__ b2) {
    const int gw   = (blockIdx.x * blockDim.x + threadIdx.x) >> 5;
    const int lane = threadIdx.x & 31;

    if (gw < FOLD_TASKS) {
        const int e = gw / 1552, j = gw - e * 1552;
        const float4* a4  = (const float4*)(w1 + ((size_t)(e * 1552 + j)) * 256);
        const float4* wb4 = (const float4*)(w2 + e * 512);
        float4 x0 = a4[lane];
        float4 x1 = a4[lane + 32];
        float4 p0 = wb4[2 * lane];        // pairs for k=4l, 4l+1
        float4 p1 = wb4[2 * lane + 1];    // pairs for k=4l+2, 4l+3
        float4 p2 = wb4[64 + 2 * lane];   // pairs for k=128+4l, +1
        float4 p3 = wb4[65 + 2 * lane];
        float a0 = x0.x*p0.x + x0.y*p0.z + x0.z*p1.x + x0.w*p1.z
                 + x1.x*p2.x + x1.y*p2.z + x1.z*p3.x + x1.w*p3.z;
        float a1 = x0.x*p0.y + x0.y*p0.w + x0.z*p1.y + x0.w*p1.w
                 + x1.x*p2.y + x1.y*p2.w + x1.z*p3.y + x1.w*p3.w;
        #pragma unroll
        for (int off = 16; off; off >>= 1) {
            a0 += __shfl_down_sync(0xffffffffu, a0, off);
            a1 += __shfl_down_sync(0xffffffffu, a1, off);
        }
        if (lane == 0) {
            g_Wc[gw * 2 + 0] = a0;
            g_Wc[gw * 2 + 1] = a1;
            if (j < HH) {                         // first-half feature -> O1 cols
                g_W19[j * 20 + 11 + e * 2 + 0] = a0;
                g_W19[j * 20 + 11 + e * 2 + 1] = a1;
            } else if (j >= 776 && j < 776 + HH) { // second-half feature -> O2 cols
                int jj = j - 776;
                g_W19[jj * 20 + 15 + e * 2 + 0] = a0;
                g_W19[jj * 20 + 15 + e * 2 + 1] = a1;
            }
        }
    } else if (gw < FOLD_TASKS + 4) {
        const int idx = gw - FOLD_TASKS;          // 0..3
        const int e = idx >> 1, c = idx & 1;
        float s = 0.f;
        for (int k = lane; k < 256; k += 32)
            s += b1[e * 256 + k] * w2[e * 512 + k * 2 + c];
        #pragma unroll
        for (int off = 16; off; off >>= 1)
            s += __shfl_down_sync(0xffffffffu, s, off);
        if (lane == 0) g_Ob[idx] = s + b2[e * 2 + c];
    } else if (gw == FOLD_TASKS + 4) {
        // speaker_ids stored int64 or int32 (values in {0,1}).
        // int64: odd 32-bit words of first 1024 words are all zero.
        const unsigned int* u = (const unsigned int*)spk_raw;
        unsigned nz = 0;
        for (int i = lane; i < ROWS; i += 32) nz |= u[2 * i + 1];
        unsigned any = __ballot_sync(0xffffffffu, nz != 0u);
        const bool w64 = (any == 0u);
        for (int i = lane; i < ROWS; i += 32)
            g_spk[i] = (float)(w64 ? u[2 * i] : u[i]);
    } else if (gw < FOLD_TASKS + 16) {
        // pack emo_w (5376) + gate_w G1 (1536) + gate_w G2 (1536) = 8448 elems
        const int pid = gw - (FOLD_TASKS + 5);    // 0..10
        for (int idx = pid * 32 + lane; idx < 8448; idx += 11 * 32) {
            if (idx < 5376) {
                int j = idx / 7, c = idx - j * 7;
                g_W19[j * 20 + c] = emo_w[idx];
            } else if (idx < 5376 + 1536) {
                int q = idx - 5376;
                int j = q >> 1, c = q & 1;
                g_W19[j * 20 + 7 + c] = gate_w[j * 2 + c];
            } else {
                int q = idx - 5376 - 1536;
                int j = q >> 1, c = q & 1;
                g_W19[j * 20 + 9 + c] = gate_w[(776 + j) * 2 + c];
            }
        }
    }
}

// ================= kernel B: per-batch table + pairs ========================
// grid 128 x 256: block = (batch b = blk/8, slice s = blk%8).
// Warp w computes row i = b*64 + s*8 + w (one utterance) -> g_T + emotion out.
// Then per-batch monotonic-ticket sync (8 blocks/counter), then 260 pairs/block.
__global__ void __launch_bounds__(256)
solve_kernel(const float* __restrict__ pooled,
             const float* __restrict__ emo_b,
             const float* __restrict__ gate_w,
             const float* __restrict__ gate_b,
             float* __restrict__ out_emo,     // [1024*7]
             float* __restrict__ out_cause) { // [33280*2]
    const int tid  = threadIdx.x;
    const int lane = tid & 31;
    const int warp = tid >> 5;
    const int b = blockIdx.x >> 3;
    const int s = blockIdx.x & 7;

    // ---- table phase: one row per warp ----
    {
        const int i = b * DD + s * 8 + warp;
        const float* row = pooled + (size_t)i * HH;

        float acc[19];
        #pragma unroll
        for (int m = 0; m < 19; m++) acc[m] = 0.f;

        #pragma unroll 4
        for (int j = lane; j < HH; j += 32) {
            float x = row[j];
            const float4* wr = (const float4*)(g_W19 + j * 20);
            float4 v0 = wr[0], v1 = wr[1], v2 = wr[2], v3 = wr[3], v4 = wr[4];
            acc[0]  += x * v0.x; acc[1]  += x * v0.y; acc[2]  += x * v0.z; acc[3]  += x * v0.w;
            acc[4]  += x * v1.x; acc[5]  += x * v1.y; acc[6]  += x * v1.z; acc[7]  += x * v1.w;
            acc[8]  += x * v2.x; acc[9]  += x * v2.y; acc[10] += x * v2.z; acc[11] += x * v2.w;
            acc[12] += x * v3.x; acc[13] += x * v3.y; acc[14] += x * v3.z; acc[15] += x * v3.w;
            acc[16] += x * v4.x; acc[17] += x * v4.y; acc[18] += x * v4.z;
        }

        #pragma unroll
        for (int off = 16; off; off >>= 1) {
            #pragma unroll
            for (int m = 0; m < 19; m++)
                acc[m] += __shfl_down_sync(0xffffffffu, acc[m], off);
        }

        if (lane == 0) {
            float ep[7];
            #pragma unroll
            for (int c = 0; c < 7; c++) {
                ep[c] = acc[c] + emo_b[c];
                out_emo[(size_t)i * 7 + c] = ep[c];
            }
            const float spkv = g_spk[i];
            #pragma unroll
            for (int m = 0; m < 12; m++) {
                float v = acc[7 + m];
                #pragma unroll
                for (int f = 768; f < 776; f++) {
                    float xf = (f == 775) ? spkv : ep[f - 768];
                    float w;
                    if (m < 2)       w = gate_w[f * 2 + m];
                    else if (m < 4)  w = gate_w[(776 + f) * 2 + (m - 2)];
                    else if (m < 8)  { int idx = m - 4; w = g_Wc[((idx >> 1) * 1552 + f) * 2 + (idx & 1)]; }
                    else             { int idx = m - 8; w = g_Wc[((idx >> 1) * 1552 + 776 + f) * 2 + (idx & 1)]; }
                    v += xf * w;
                }
                g_T[i * 12 + m] = v;
            }
        }
    }

    // ---- per-batch sync (monotonic ticket; 8 blocks per counter) ----
    __syncthreads();
    if (tid == 0) {
        __threadfence();
        unsigned t = atomicAdd(&g_cnt[b], 1u) + 1u;
        unsigned round_end = ((t + 7u) / 8u) * 8u;
        volatile unsigned int* c = &g_cnt[b];
        while (*c < round_end) { }
        __threadfence();
    }
    __syncthreads();

    // ---- pair phase: 260 pairs per block ----
    const float gb0 = gate_b[0];
    const float gb1 = gate_b[1];
    const float ob0 = g_Ob[0], ob1 = g_Ob[1], ob2 = g_Ob[2], ob3 = g_Ob[3];
    const float* Tb = g_T + b * DD * 12;

    for (int ql = tid; ql < 260; ql += 256) {
        int q = s * 260 + ql;                  // 0..2079 within batch
        int end = (int)((sqrtf(8.f * (float)q + 1.f) - 1.f) * 0.5f);
        while ((end + 1) * (end + 2) / 2 <= q) end++;
        while (end * (end + 1) / 2 > q) end--;
        int t = q - end * (end + 1) / 2;

        const float* Tt = Tb + t   * 12;
        const float* Te = Tb + end * 12;

        float g0 = Tt[0] + Te[2] + gb0;
        float g1 = Tt[1] + Te[3] + gb1;

        float o00 = Tt[4] + Te[8]  + ob0;
        float o01 = Tt[5] + Te[9]  + ob1;
        float o10 = Tt[6] + Te[10] + ob2;
        float o11 = Tt[7] + Te[11] + ob3;

        size_t p = (size_t)b * PAIRS_PER_B + q;
        out_cause[p * 2 + 0] = g0 * o00 + g1 * o10;
        out_cause[p * 2 + 1] = g0 * o01 + g1 * o11;
    }
}

// ---------------- launch ----------------
extern "C" void kernel_launch(void* const* d_in, const int* in_sizes, int n_in,
                              void* d_out, int out_size) {
    const float* pooled  = (const float*)d_in[0];
    const void*  spk     = d_in[1];
    const float* emo_w   = (const float*)d_in[2];
    const float* emo_b   = (const float*)d_in[3];
    const float* gate_w  = (const float*)d_in[4];
    const float* gate_b  = (const float*)d_in[5];
    const float* exp_w1  = (const float*)d_in[6];
    const float* exp_b1  = (const float*)d_in[7];
    const float* exp_w2  = (const float*)d_in[8];
    const float* exp_b2  = (const float*)d_in[9];
    float* out = (float*)d_out;

    prep_kernel<<<390, 256>>>(spk, emo_w, gate_w, exp_w1, exp_b1, exp_w2, exp_b2);
    solve_kernel<<<128, 256>>>(pooled, emo_b, gate_w, gate_b, out, out + ROWS * NE);
}